// round 8
// baseline (speedup 1.0000x reference)
#include <cuda_runtime.h>
#include <math.h>

#define KDIM 8192
#define BDIM 512
#define PDIM 4096

#define ACHUNK 512                 // k's per accum chunk
#define ANCH   (KDIM / 2 / ACHUNK) // 8 accum chunks per CTA (half K)
#define ANST   3                   // accum stages

// Scratch (allocation-free rule: __device__ globals)
__device__ float g_Apart[2 * BDIM * 10];   // per-CTA partial A
__device__ unsigned int g_pflag[2 * BDIM]; // per-CTA publish flags (peer-cleared)
__device__ float g_part[2 * BDIM];         // per-CTA point partial sums
__device__ unsigned int g_cnt;             // last-block-done counter (self-reset)

__device__ __forceinline__ float warpSum(float v) {
    #pragma unroll
    for (int o = 16; o; o >>= 1) v += __shfl_xor_sync(0xffffffffu, v, o);
    return v;
}

// cp.async helpers (16B, cache-global)
__device__ __forceinline__ void cpa16(unsigned dst, const void* src) {
    asm volatile("cp.async.cg.shared.global [%0], [%1], 16;" :: "r"(dst), "l"(src));
}
__device__ __forceinline__ void cpa_commit() {
    asm volatile("cp.async.commit_group;");
}
template <int N>
__device__ __forceinline__ void cpa_wait() {
    asm volatile("cp.async.wait_group %0;" :: "n"(N));
}
__device__ __forceinline__ unsigned smem_u32(const void* p) {
    return (unsigned)__cvta_generic_to_shared(p);
}

// FMA/ALU-pipe exp (no MUFU). |x| <= ~20, rel err ~1.5e-7.
__device__ __forceinline__ float fexp(float x) {
    float t  = x * 1.4426950408889634f;
    float fn = t + 12582912.0f;
    int   n  = __float_as_int(fn) - 0x4B400000;
    float r  = t - (fn - 12582912.0f);
    float p = 1.5403530393e-4f;
    p = fmaf(p, r, 1.3333558146e-3f);
    p = fmaf(p, r, 9.6181291076e-3f);
    p = fmaf(p, r, 5.5504108665e-2f);
    p = fmaf(p, r, 2.4022650696e-1f);
    p = fmaf(p, r, 6.9314718056e-1f);
    p = fmaf(p, r, 1.0f);
    return __int_as_float(__float_as_int(p) + (n << 23));
}

// FMA/ALU-pipe sqrt: magic rsqrt + 2 Newton iters, then c * rsqrt(c).
__device__ __forceinline__ float fsqrt_fma(float c) {
    float y = __int_as_float(0x5f3759df - (__float_as_int(c) >> 1));
    float h = 0.5f * c;
    y = y * fmaf(-h * y, y, 1.5f);
    y = y * fmaf(-h * y, y, 1.5f);
    return c * y;
}

__device__ __forceinline__ void quat2mat(const float qv[4], float mm[9]) {
    float r = qv[0], i = qv[1], j = qv[2], k = qv[3];
    float two_s = __fdividef(2.0f, r * r + i * i + j * j + k * k);
    mm[0] = 1.0f - two_s * (j * j + k * k);
    mm[1] = two_s * (i * j - k * r);
    mm[2] = two_s * (i * k + j * r);
    mm[3] = two_s * (i * j + k * r);
    mm[4] = 1.0f - two_s * (i * i + k * k);
    mm[5] = two_s * (j * k - i * r);
    mm[6] = two_s * (i * k - j * r);
    mm[7] = two_s * (j * k + i * r);
    mm[8] = 1.0f - two_s * (i * i + j * j);
}

// ---------------------------------------------------------------------------
// Fused kernel, 2 CTAs per batch (grid 1024), one full wave at 7 CTAs/SM.
// Each CTA: 8-chunk cp.async accum over its half of K -> partial A -> publish
// + peer-exchange (flag set by owner, cleared by peer) -> redundant identical
// Jacobi eig in both CTAs (overlapped with its point-chunk cp.asyncs) ->
// 2 point chunks -> per-CTA partial -> last-of-1024 deterministic mean.
// ---------------------------------------------------------------------------
__global__ __launch_bounds__(256, 7) void k_fused(const float* __restrict__ s,
                                                  const float* __restrict__ q,
                                                  const float* __restrict__ gt,
                                                  const float* __restrict__ point,
                                                  float* __restrict__ out) {
    const int blk  = blockIdx.x;
    const int b    = blk >> 1;
    const int half = blk & 1;
    const int t    = threadIdx.x;

    __shared__ float4 sq[ANST][ACHUNK];       // 24 KB q stages (reused for points)
    __shared__ float  ss[ANST][ACHUNK];       // 6 KB  s stages
    __shared__ float red[80];
    __shared__ float Ms[9];
    __shared__ int isLast;

    const size_t kbase = (size_t)b * KDIM + (size_t)half * (KDIM / 2);
    const float4* __restrict__ gq = (const float4*)(q + kbase * 4);
    const float4* __restrict__ gs = (const float4*)(s + kbase);
    const float4* __restrict__ gp =
        (const float4*)(point + ((size_t)b * PDIM + (size_t)half * (PDIM / 2)) * 3);

    // Issue accum chunk c into stage st (q: 2/thread, s: 1 for t<128)
    auto issueA = [&](int c, int st) {
        unsigned dq = smem_u32(&sq[st][0]);
        const float4* srcq = gq + c * ACHUNK;
        cpa16(dq + t * 16,         srcq + t);
        cpa16(dq + (t + 256) * 16, srcq + t + 256);
        if (t < 128) {
            unsigned ds = smem_u32(&ss[st][0]);
            cpa16(ds + t * 16, gs + c * (ACHUNK / 4) + t);
        }
        cpa_commit();
    };
    // Issue a 768-float4 point chunk (3 cp.async / thread)
    auto issueP = [&](const float4* dstBase, int chunk) {
        unsigned d = smem_u32(dstBase);
        const float4* src = gp + chunk * 768;
        cpa16(d + t * 16,          src + t);
        cpa16(d + (t + 256) * 16,  src + t + 256);
        cpa16(d + (t + 512) * 16,  src + t + 512);
        cpa_commit();
    };

    issueA(0, 0);
    issueA(1, 1);
    issueA(2, 2);

    float a0 = 0.f, a1 = 0.f, a2 = 0.f, a3 = 0.f, a4 = 0.f;
    float a5 = 0.f, a6 = 0.f, a7 = 0.f, a8 = 0.f, a9 = 0.f;

    #pragma unroll 4
    for (int c = 0; c < ANCH; c++) {
        if (c < ANCH - 2)       cpa_wait<2>();   // A_c retired
        else if (c == ANCH - 2) cpa_wait<1>();
        else                    cpa_wait<0>();
        __syncthreads();

        const int st = c % ANST;
        const float4* q4s = &sq[st][0];
        float4 qa = q4s[t];
        float4 qb = q4s[t + 256];
        float w0 = fexp(ss[st][t]);
        float w1 = fexp(ss[st][t + 256]);
        {
            float wr = w0 * qa.x, wi = w0 * qa.y, wj = w0 * qa.z, wk = w0 * qa.w;
            a0 += wr * qa.x; a1 += wr * qa.y; a2 += wr * qa.z; a3 += wr * qa.w;
            a4 += wi * qa.y; a5 += wi * qa.z; a6 += wi * qa.w;
            a7 += wj * qa.z; a8 += wj * qa.w; a9 += wk * qa.w;
        }
        {
            float wr = w1 * qb.x, wi = w1 * qb.y, wj = w1 * qb.z, wk = w1 * qb.w;
            a0 += wr * qb.x; a1 += wr * qb.y; a2 += wr * qb.z; a3 += wr * qb.w;
            a4 += wi * qb.y; a5 += wi * qb.z; a6 += wi * qb.w;
            a7 += wj * qb.z; a8 += wj * qb.w; a9 += wk * qb.w;
        }
        __syncthreads();
        if (c + 3 < ANCH) issueA(c + 3, (c + 3) % ANST);
    }

    // Deterministic block reduction of the 10 accumulators.
    float acc[10] = {a0, a1, a2, a3, a4, a5, a6, a7, a8, a9};
    #pragma unroll
    for (int i = 0; i < 10; i++) acc[i] = warpSum(acc[i]);
    const int w = t >> 5, l = t & 31;
    if (l == 0) {
        #pragma unroll
        for (int i = 0; i < 10; i++) red[w * 10 + i] = acc[i];
    }
    __syncthreads();   // red ready; sq/ss free

    // Point buffers reuse the accum smem (all cp.async groups drained).
    float4* sp0 = &sq[0][0];
    float4* sp1 = &sq[0][0] + 768;
    issueP(sp0, 0);
    issueP(sp1, 1);

    // Thread 0: publish partial A, exchange with peer CTA, redundant eig.
    // (Peer exchange + eig overlap with the in-flight point cp.asyncs.)
    if (t == 0) {
        float mine[10];
        #pragma unroll
        for (int i = 0; i < 10; i++) {
            float sA = 0.f;
            #pragma unroll
            for (int w2 = 0; w2 < 8; w2++) sA += red[w2 * 10 + i];
            mine[i] = sA;
            g_Apart[(size_t)blk * 10 + i] = sA;
        }
        __threadfence();
        atomicExch(&g_pflag[blk], 1u);       // release own partial

        const int peer = blk ^ 1;
        while (atomicAdd(&g_pflag[peer], 0u) == 0u) { }   // acquire peer
        __threadfence();
        float theirs[10];
        #pragma unroll
        for (int i = 0; i < 10; i++) theirs[i] = g_Apart[(size_t)peer * 10 + i];
        atomicExch(&g_pflag[peer], 0u);      // clear PEER's flag (replay-safe)

        // Deterministic order: half0 + half1.
        float A[10];
        #pragma unroll
        for (int i = 0; i < 10; i++)
            A[i] = half ? (theirs[i] + mine[i]) : (mine[i] + theirs[i]);

        float a[4][4], v[4][4];
        a[0][0] = A[0];
        a[0][1] = a[1][0] = A[1];
        a[0][2] = a[2][0] = A[2];
        a[0][3] = a[3][0] = A[3];
        a[1][1] = A[4];
        a[1][2] = a[2][1] = A[5];
        a[1][3] = a[3][1] = A[6];
        a[2][2] = A[7];
        a[2][3] = a[3][2] = A[8];
        a[3][3] = A[9];
        #pragma unroll
        for (int i = 0; i < 4; i++)
            #pragma unroll
            for (int j = 0; j < 4; j++) v[i][j] = (i == j) ? 1.0f : 0.0f;

        const int PP[6] = {0, 0, 0, 1, 1, 2};
        const int QQ[6] = {1, 2, 3, 2, 3, 3};

        for (int sweep = 0; sweep < 6; sweep++) {
            #pragma unroll
            for (int pair = 0; pair < 6; pair++) {
                int p = PP[pair], qi = QQ[pair];
                float apq = a[p][qi];
                if (fabsf(apq) > 1e-30f) {
                    float theta = __fdividef(a[qi][qi] - a[p][p], 2.0f * apq);
                    float tt = __fdividef(1.0f, fabsf(theta) + sqrtf(theta * theta + 1.0f));
                    if (theta < 0.0f) tt = -tt;
                    float c = rsqrtf(tt * tt + 1.0f);
                    float sn = tt * c;
                    float app = a[p][p], aqq = a[qi][qi];
                    a[p][p] = app - tt * apq;
                    a[qi][qi] = aqq + tt * apq;
                    a[p][qi] = a[qi][p] = 0.0f;
                    #pragma unroll
                    for (int r = 0; r < 4; r++) {
                        if (r != p && r != qi) {
                            float arp = a[r][p], arq = a[r][qi];
                            a[r][p] = a[p][r] = c * arp - sn * arq;
                            a[r][qi] = a[qi][r] = sn * arp + c * arq;
                        }
                    }
                    #pragma unroll
                    for (int r = 0; r < 4; r++) {
                        float vrp = v[r][p], vrq = v[r][qi];
                        v[r][p] = c * vrp - sn * vrq;
                        v[r][qi] = sn * vrp + c * vrq;
                    }
                }
            }
        }

        int best = 0;
        float bv = a[0][0];
        #pragma unroll
        for (int i = 1; i < 4; i++)
            if (a[i][i] > bv) { bv = a[i][i]; best = i; }

        float qp[4] = {v[0][best], v[1][best], v[2][best], v[3][best]};
        // sign/norm of qp irrelevant: quat2mat divides by |q|^2 and is even in q
        float mp[9], mg[9];
        quat2mat(qp, mp);
        float qg[4] = {gt[b * 4 + 0], gt[b * 4 + 1], gt[b * 4 + 2], gt[b * 4 + 3]};
        quat2mat(qg, mg);
        #pragma unroll
        for (int i = 0; i < 9; i++) Ms[i] = mp[i] - mg[i];
    }
    __syncthreads();   // Ms visible
    const float M0 = Ms[0], M1 = Ms[1], M2 = Ms[2];
    const float M3 = Ms[3], M4 = Ms[4], M5 = Ms[5];
    const float M6 = Ms[6], M7 = Ms[7], M8 = Ms[8];

    float pacc = 0.f;
    auto consumeP = [&](const float4* P) {
        float4 v0 = P[3 * t + 0];
        float4 v1 = P[3 * t + 1];
        float4 v2 = P[3 * t + 2];
        float px[4] = {v0.x, v0.w, v1.z, v2.y};
        float py[4] = {v0.y, v1.x, v1.w, v2.z};
        float pz[4] = {v0.z, v1.y, v2.x, v2.w};
        #pragma unroll
        for (int r = 0; r < 4; r++) {
            float x = px[r], y = py[r], z = pz[r];
            float dx = x * M0 + y * M3 + z * M6;
            float dy = x * M1 + y * M4 + z * M7;
            float dz = x * M2 + y * M5 + z * M8;
            pacc += fsqrt_fma(dx * dx + dy * dy + dz * dz);
        }
    };

    cpa_wait<1>();     // P0 done (P1 may pend)
    __syncthreads();
    consumeP(sp0);
    cpa_wait<0>();     // P1 done
    __syncthreads();
    consumeP(sp1);

    // Block reduction of point sum.
    pacc = warpSum(pacc);
    if (l == 0) red[w] = pacc;
    __syncthreads();
    if (t < 32) {
        float x = (t < 8) ? red[t] : 0.f;
        x = warpSum(x);
        if (t == 0) g_part[blk] = x;
    }

    // Last-block-done final reduction (deterministic fixed-order sum).
    if (t == 0) {
        __threadfence();
        unsigned int prev = atomicAdd(&g_cnt, 1u);
        isLast = (prev == 2u * BDIM - 1u);
    }
    __syncthreads();
    if (isLast) {
        float sfin = g_part[t] + g_part[t + 256] + g_part[t + 512] + g_part[t + 768];
        sfin = warpSum(sfin);
        if ((t & 31) == 0) red[t >> 5] = sfin;
        __syncthreads();
        if (t < 32) {
            float x = (t < 8) ? red[t] : 0.f;
            x = warpSum(x);
            if (t == 0) {
                out[0] = x * (1.0f / ((float)BDIM * (float)PDIM));
                g_cnt = 0u;   // reset for next graph replay
            }
        }
    }
}

extern "C" void kernel_launch(void* const* d_in, const int* in_sizes, int n_in,
                              void* d_out, int out_size) {
    const float* s     = (const float*)d_in[0];  // softEncodePred (B,K)
    const float* q     = (const float*)d_in[1];  // oriHistogramMap (B,K,4)
    const float* gt    = (const float*)d_in[2];  // gt (B,4)
    const float* point = (const float*)d_in[3];  // point (B,P,3)
    float* out = (float*)d_out;

    k_fused<<<2 * BDIM, 256>>>(s, q, gt, point, out);
}

// round 9
// speedup vs baseline: 1.1511x; 1.1511x over previous
#include <cuda_runtime.h>
#include <math.h>

#define KDIM 8192
#define BDIM 512
#define PDIM 4096

#define ACHUNK 512                 // k's per accum chunk
#define ANCH   (KDIM / ACHUNK)     // 16 accum chunks
#define ANST   5                   // q stages (8 KB each)

// Scratch (allocation-free rule: __device__ globals)
__device__ float g_part[BDIM];       // per-block point partial sums
__device__ unsigned int g_cnt;       // last-block-done counter (self-reset)

__device__ __forceinline__ float warpSum(float v) {
    #pragma unroll
    for (int o = 16; o; o >>= 1) v += __shfl_xor_sync(0xffffffffu, v, o);
    return v;
}

// cp.async helpers (16B, cache-global)
__device__ __forceinline__ void cpa16(unsigned dst, const void* src) {
    asm volatile("cp.async.cg.shared.global [%0], [%1], 16;" :: "r"(dst), "l"(src));
}
__device__ __forceinline__ void cpa_commit() {
    asm volatile("cp.async.commit_group;");
}
template <int N>
__device__ __forceinline__ void cpa_wait() {
    asm volatile("cp.async.wait_group %0;" :: "n"(N));
}
__device__ __forceinline__ unsigned smem_u32(const void* p) {
    return (unsigned)__cvta_generic_to_shared(p);
}

// FMA/ALU-pipe exp (no MUFU). |x| <= ~20, rel err ~1.5e-7.
__device__ __forceinline__ float fexp(float x) {
    float t  = x * 1.4426950408889634f;
    float fn = t + 12582912.0f;
    int   n  = __float_as_int(fn) - 0x4B400000;
    float r  = t - (fn - 12582912.0f);
    float p = 1.5403530393e-4f;
    p = fmaf(p, r, 1.3333558146e-3f);
    p = fmaf(p, r, 9.6181291076e-3f);
    p = fmaf(p, r, 5.5504108665e-2f);
    p = fmaf(p, r, 2.4022650696e-1f);
    p = fmaf(p, r, 6.9314718056e-1f);
    p = fmaf(p, r, 1.0f);
    return __int_as_float(__float_as_int(p) + (n << 23));
}

// FMA/ALU-pipe sqrt: magic rsqrt + 2 Newton iters, then c * rsqrt(c).
__device__ __forceinline__ float fsqrt_fma(float c) {
    float y = __int_as_float(0x5f3759df - (__float_as_int(c) >> 1));
    float h = 0.5f * c;
    y = y * fmaf(-h * y, y, 1.5f);
    y = y * fmaf(-h * y, y, 1.5f);
    return c * y;
}

__device__ __forceinline__ void quat2mat(const float qv[4], float mm[9]) {
    float r = qv[0], i = qv[1], j = qv[2], k = qv[3];
    float two_s = __fdividef(2.0f, r * r + i * i + j * j + k * k);
    mm[0] = 1.0f - two_s * (j * j + k * k);
    mm[1] = two_s * (i * j - k * r);
    mm[2] = two_s * (i * k + j * r);
    mm[3] = two_s * (i * j + k * r);
    mm[4] = 1.0f - two_s * (i * i + k * k);
    mm[5] = two_s * (j * k - i * r);
    mm[6] = two_s * (i * k - j * r);
    mm[7] = two_s * (j * k + i * r);
    mm[8] = 1.0f - two_s * (i * i + j * j);
}

// ---------------------------------------------------------------------------
// One fused kernel, one CTA per batch (grid 512).
// Accum: 5-stage cp.async pipeline (q only; wait<3> => 4 outstanding 8 KB
// groups = 32 KB in flight per CTA). s streamed via double-buffered LDG regs.
// Then block-reduce A, issue 3 point-chunk cp.asyncs into the freed q smem,
// thread-0 Jacobi eig overlapped, consume 4 point chunks, last-block mean.
// ---------------------------------------------------------------------------
__global__ __launch_bounds__(256) void k_fused(const float* __restrict__ s,
                                               const float* __restrict__ q,
                                               const float* __restrict__ gt,
                                               const float* __restrict__ point,
                                               float* __restrict__ out) {
    const int b = blockIdx.x;
    const int t = threadIdx.x;

    __shared__ float4 sq[ANST][ACHUNK];       // 40 KB q stages (reused for points)
    __shared__ float red[80];
    __shared__ float Ms[9];
    __shared__ int isLast;

    const float4* __restrict__ gq = (const float4*)(q + (size_t)b * KDIM * 4);
    const float*  __restrict__ gsf = s + (size_t)b * KDIM;
    const float4* __restrict__ gp = (const float4*)(point + (size_t)b * PDIM * 3);

    // Issue accum q-chunk c into stage st (2 cp.async / thread)
    auto issueA = [&](int c, int st) {
        unsigned dq = smem_u32(&sq[st][0]);
        const float4* srcq = gq + c * ACHUNK;
        cpa16(dq + t * 16,         srcq + t);
        cpa16(dq + (t + 256) * 16, srcq + t + 256);
        cpa_commit();
    };
    // Issue a 768-float4 point chunk (3 cp.async / thread)
    auto issueP = [&](const float4* dstBase, int chunk) {
        unsigned d = smem_u32(dstBase);
        const float4* src = gp + chunk * 768;
        cpa16(d + t * 16,          src + t);
        cpa16(d + (t + 256) * 16,  src + t + 256);
        cpa16(d + (t + 512) * 16,  src + t + 512);
        cpa_commit();
    };

    // Pre-issue 4 q chunks; prefetch s for chunks 0 and 1 into registers.
    issueA(0, 0);
    issueA(1, 1);
    issueA(2, 2);
    issueA(3, 3);
    float sc0 = gsf[t], sc1 = gsf[t + 256];                  // chunk 0
    float sn0 = gsf[ACHUNK + t], sn1 = gsf[ACHUNK + t + 256]; // chunk 1

    float a0 = 0.f, a1 = 0.f, a2 = 0.f, a3 = 0.f, a4 = 0.f;
    float a5 = 0.f, a6 = 0.f, a7 = 0.f, a8 = 0.f, a9 = 0.f;

    #pragma unroll
    for (int c = 0; c < ANCH; c++) {
        // Committed before wait at iter c: A0..A_{c+3}. wait<3> retires A_c.
        if (c < ANCH - 3)       cpa_wait<3>();
        else if (c == ANCH - 3) cpa_wait<2>();
        else if (c == ANCH - 2) cpa_wait<1>();
        else                    cpa_wait<0>();
        __syncthreads();

        // Prefetch s for chunk c+2 (overlaps with consume below).
        float sp0r = 0.f, sp1r = 0.f;
        if (c + 2 < ANCH) {
            sp0r = gsf[(c + 2) * ACHUNK + t];
            sp1r = gsf[(c + 2) * ACHUNK + t + 256];
        }

        const int st = c % ANST;
        const float4* q4s = &sq[st][0];
        float4 qa = q4s[t];
        float4 qb = q4s[t + 256];
        float w0 = fexp(sc0);
        float w1 = fexp(sc1);
        {
            float wr = w0 * qa.x, wi = w0 * qa.y, wj = w0 * qa.z, wk = w0 * qa.w;
            a0 += wr * qa.x; a1 += wr * qa.y; a2 += wr * qa.z; a3 += wr * qa.w;
            a4 += wi * qa.y; a5 += wi * qa.z; a6 += wi * qa.w;
            a7 += wj * qa.z; a8 += wj * qa.w; a9 += wk * qa.w;
        }
        {
            float wr = w1 * qb.x, wi = w1 * qb.y, wj = w1 * qb.z, wk = w1 * qb.w;
            a0 += wr * qb.x; a1 += wr * qb.y; a2 += wr * qb.z; a3 += wr * qb.w;
            a4 += wi * qb.y; a5 += wi * qb.z; a6 += wi * qb.w;
            a7 += wj * qb.z; a8 += wj * qb.w; a9 += wk * qb.w;
        }
        __syncthreads();   // all threads done reading stage st
        if (c + 4 < ANCH) issueA(c + 4, (c + 4) % ANST);

        // Rotate s double-buffer.
        sc0 = sn0; sc1 = sn1;
        sn0 = sp0r; sn1 = sp1r;
    }

    // Deterministic block reduction of the 10 accumulators.
    float acc[10] = {a0, a1, a2, a3, a4, a5, a6, a7, a8, a9};
    #pragma unroll
    for (int i = 0; i < 10; i++) acc[i] = warpSum(acc[i]);
    const int w = t >> 5, l = t & 31;
    if (l == 0) {
        #pragma unroll
        for (int i = 0; i < 10; i++) red[w * 10 + i] = acc[i];
    }
    __syncthreads();   // red ready; sq free (all accum groups drained)

    // Point buffers inside the 40 KB q region (3 x 768 float4 = 36 KB).
    float4* sp0 = &sq[0][0];
    float4* sp1 = &sq[0][0] + 768;
    float4* sp2 = &sq[0][0] + 1536;
    issueP(sp0, 0);    // P0
    issueP(sp1, 1);    // P1
    issueP(sp2, 2);    // P2

    // Thread 0: finish A, Jacobi eig, quat->mat difference -> Ms
    // (runs while P0/P1/P2 cp.asyncs are in flight).
    if (t == 0) {
        float A[10];
        #pragma unroll
        for (int i = 0; i < 10; i++) {
            float sA = 0.f;
            #pragma unroll
            for (int w2 = 0; w2 < 8; w2++) sA += red[w2 * 10 + i];
            A[i] = sA;
        }

        float a[4][4], v[4][4];
        a[0][0] = A[0];
        a[0][1] = a[1][0] = A[1];
        a[0][2] = a[2][0] = A[2];
        a[0][3] = a[3][0] = A[3];
        a[1][1] = A[4];
        a[1][2] = a[2][1] = A[5];
        a[1][3] = a[3][1] = A[6];
        a[2][2] = A[7];
        a[2][3] = a[3][2] = A[8];
        a[3][3] = A[9];
        #pragma unroll
        for (int i = 0; i < 4; i++)
            #pragma unroll
            for (int j = 0; j < 4; j++) v[i][j] = (i == j) ? 1.0f : 0.0f;

        const int PP[6] = {0, 0, 0, 1, 1, 2};
        const int QQ[6] = {1, 2, 3, 2, 3, 3};

        for (int sweep = 0; sweep < 6; sweep++) {
            #pragma unroll
            for (int pair = 0; pair < 6; pair++) {
                int p = PP[pair], qi = QQ[pair];
                float apq = a[p][qi];
                if (fabsf(apq) > 1e-30f) {
                    float theta = __fdividef(a[qi][qi] - a[p][p], 2.0f * apq);
                    float tt = __fdividef(1.0f, fabsf(theta) + sqrtf(theta * theta + 1.0f));
                    if (theta < 0.0f) tt = -tt;
                    float c = rsqrtf(tt * tt + 1.0f);
                    float sn = tt * c;
                    float app = a[p][p], aqq = a[qi][qi];
                    a[p][p] = app - tt * apq;
                    a[qi][qi] = aqq + tt * apq;
                    a[p][qi] = a[qi][p] = 0.0f;
                    #pragma unroll
                    for (int r = 0; r < 4; r++) {
                        if (r != p && r != qi) {
                            float arp = a[r][p], arq = a[r][qi];
                            a[r][p] = a[p][r] = c * arp - sn * arq;
                            a[r][qi] = a[qi][r] = sn * arp + c * arq;
                        }
                    }
                    #pragma unroll
                    for (int r = 0; r < 4; r++) {
                        float vrp = v[r][p], vrq = v[r][qi];
                        v[r][p] = c * vrp - sn * vrq;
                        v[r][qi] = sn * vrp + c * vrq;
                    }
                }
            }
        }

        int best = 0;
        float bv = a[0][0];
        #pragma unroll
        for (int i = 1; i < 4; i++)
            if (a[i][i] > bv) { bv = a[i][i]; best = i; }

        float qp[4] = {v[0][best], v[1][best], v[2][best], v[3][best]};
        // sign/norm of qp irrelevant: quat2mat divides by |q|^2 and is even in q
        float mp[9], mg[9];
        quat2mat(qp, mp);
        float qg[4] = {gt[b * 4 + 0], gt[b * 4 + 1], gt[b * 4 + 2], gt[b * 4 + 3]};
        quat2mat(qg, mg);
        #pragma unroll
        for (int i = 0; i < 9; i++) Ms[i] = mp[i] - mg[i];
    }
    __syncthreads();   // Ms visible; P0/P1/P2 committed by all threads
    const float M0 = Ms[0], M1 = Ms[1], M2 = Ms[2];
    const float M3 = Ms[3], M4 = Ms[4], M5 = Ms[5];
    const float M6 = Ms[6], M7 = Ms[7], M8 = Ms[8];

    // Consume one 1024-point chunk from an smem region.
    float pacc = 0.f;
    auto consumeP = [&](const float4* P) {
        float4 v0 = P[3 * t + 0];
        float4 v1 = P[3 * t + 1];
        float4 v2 = P[3 * t + 2];
        float px[4] = {v0.x, v0.w, v1.z, v2.y};
        float py[4] = {v0.y, v1.x, v1.w, v2.z};
        float pz[4] = {v0.z, v1.y, v2.x, v2.w};
        #pragma unroll
        for (int r = 0; r < 4; r++) {
            float x = px[r], y = py[r], z = pz[r];
            float dx = x * M0 + y * M3 + z * M6;
            float dy = x * M1 + y * M4 + z * M7;
            float dz = x * M2 + y * M5 + z * M8;
            pacc += fsqrt_fma(dx * dx + dy * dy + dz * dz);
        }
    };

    cpa_wait<2>();             // pending <= 2 {P1,P2} => P0 done
    __syncthreads();
    consumeP(sp0);             // chunk 0
    __syncthreads();           // all threads done reading sp0
    issueP(sp0, 3);            // P3 reuses sp0
    cpa_wait<2>();             // pending <= 2 {P2,P3} => P1 done
    __syncthreads();
    consumeP(sp1);             // chunk 1
    cpa_wait<1>();             // P2 done
    __syncthreads();
    consumeP(sp2);             // chunk 2
    cpa_wait<0>();             // P3 done
    __syncthreads();
    consumeP(sp0);             // chunk 3

    // Block reduction of point sum.
    pacc = warpSum(pacc);
    if (l == 0) red[w] = pacc;
    __syncthreads();
    if (t < 32) {
        float x = (t < 8) ? red[t] : 0.f;
        x = warpSum(x);
        if (t == 0) g_part[b] = x;
    }

    // Last-block-done final reduction (deterministic fixed-order sum).
    if (t == 0) {
        __threadfence();
        unsigned int prev = atomicAdd(&g_cnt, 1u);
        isLast = (prev == (unsigned)(BDIM - 1));
    }
    __syncthreads();
    if (isLast) {
        float sfin = g_part[t] + g_part[t + 256];
        sfin = warpSum(sfin);
        if ((t & 31) == 0) red[t >> 5] = sfin;
        __syncthreads();
        if (t < 32) {
            float x = (t < 8) ? red[t] : 0.f;
            x = warpSum(x);
            if (t == 0) {
                out[0] = x * (1.0f / ((float)BDIM * (float)PDIM));
                g_cnt = 0u;   // reset for next graph replay
            }
        }
    }
}

extern "C" void kernel_launch(void* const* d_in, const int* in_sizes, int n_in,
                              void* d_out, int out_size) {
    const float* s     = (const float*)d_in[0];  // softEncodePred (B,K)
    const float* q     = (const float*)d_in[1];  // oriHistogramMap (B,K,4)
    const float* gt    = (const float*)d_in[2];  // gt (B,4)
    const float* point = (const float*)d_in[3];  // point (B,P,3)
    float* out = (float*)d_out;

    k_fused<<<BDIM, 256>>>(s, q, gt, point, out);
}

// round 10
// speedup vs baseline: 1.1525x; 1.0012x over previous
#include <cuda_runtime.h>
#include <math.h>
#include <stdint.h>

#define KDIM 8192
#define BDIM 512
#define PDIM 4096

#define ACHUNK 512                 // k's per accum chunk
#define ANCH   (KDIM / ACHUNK)     // 16 accum chunks
#define ANST   5                   // q stages (8 KB each)

// Scratch (allocation-free rule: __device__ globals)
__device__ float g_part[BDIM];       // per-block point partial sums
__device__ unsigned int g_cnt;       // last-block-done counter (self-reset)

__device__ __forceinline__ float warpSum(float v) {
    #pragma unroll
    for (int o = 16; o; o >>= 1) v += __shfl_xor_sync(0xffffffffu, v, o);
    return v;
}

// L2 evict_last policy: bias the whole (104 MB < 126 MB L2) input set to
// persist across graph replays.
__device__ __forceinline__ uint64_t mkpolicy_evict_last() {
    uint64_t p;
    asm("createpolicy.fractional.L2::evict_last.b64 %0, 1.0;" : "=l"(p));
    return p;
}

// cp.async helpers (16B, cache-global, L2 evict_last hint)
__device__ __forceinline__ void cpa16(unsigned dst, const void* src, uint64_t pol) {
    asm volatile("cp.async.cg.shared.global.L2::cache_hint [%0], [%1], 16, %2;"
                 :: "r"(dst), "l"(src), "l"(pol));
}
__device__ __forceinline__ void cpa_commit() {
    asm volatile("cp.async.commit_group;");
}
template <int N>
__device__ __forceinline__ void cpa_wait() {
    asm volatile("cp.async.wait_group %0;" :: "n"(N));
}
__device__ __forceinline__ unsigned smem_u32(const void* p) {
    return (unsigned)__cvta_generic_to_shared(p);
}
// LDG with L2 evict_last hint
__device__ __forceinline__ float ldg_el(const float* p, uint64_t pol) {
    float v;
    asm volatile("ld.global.L2::cache_hint.f32 %0, [%1], %2;"
                 : "=f"(v) : "l"(p), "l"(pol));
    return v;
}

// FMA/ALU-pipe exp (no MUFU). |x| <= ~20, rel err ~1.5e-7.
__device__ __forceinline__ float fexp(float x) {
    float t  = x * 1.4426950408889634f;
    float fn = t + 12582912.0f;
    int   n  = __float_as_int(fn) - 0x4B400000;
    float r  = t - (fn - 12582912.0f);
    float p = 1.5403530393e-4f;
    p = fmaf(p, r, 1.3333558146e-3f);
    p = fmaf(p, r, 9.6181291076e-3f);
    p = fmaf(p, r, 5.5504108665e-2f);
    p = fmaf(p, r, 2.4022650696e-1f);
    p = fmaf(p, r, 6.9314718056e-1f);
    p = fmaf(p, r, 1.0f);
    return __int_as_float(__float_as_int(p) + (n << 23));
}

// FMA/ALU-pipe sqrt: magic rsqrt + 2 Newton iters, then c * rsqrt(c).
__device__ __forceinline__ float fsqrt_fma(float c) {
    float y = __int_as_float(0x5f3759df - (__float_as_int(c) >> 1));
    float h = 0.5f * c;
    y = y * fmaf(-h * y, y, 1.5f);
    y = y * fmaf(-h * y, y, 1.5f);
    return c * y;
}

__device__ __forceinline__ void quat2mat(const float qv[4], float mm[9]) {
    float r = qv[0], i = qv[1], j = qv[2], k = qv[3];
    float two_s = __fdividef(2.0f, r * r + i * i + j * j + k * k);
    mm[0] = 1.0f - two_s * (j * j + k * k);
    mm[1] = two_s * (i * j - k * r);
    mm[2] = two_s * (i * k + j * r);
    mm[3] = two_s * (i * j + k * r);
    mm[4] = 1.0f - two_s * (i * i + k * k);
    mm[5] = two_s * (j * k - i * r);
    mm[6] = two_s * (i * k - j * r);
    mm[7] = two_s * (j * k + i * r);
    mm[8] = 1.0f - two_s * (i * i + j * j);
}

// ---------------------------------------------------------------------------
// One fused kernel, one CTA per batch (grid 512). Identical to R9 except all
// input reads carry an L2::evict_last cache hint so the 104 MB input set
// persists in the 126 MB L2 across graph replays.
// ---------------------------------------------------------------------------
__global__ __launch_bounds__(256) void k_fused(const float* __restrict__ s,
                                               const float* __restrict__ q,
                                               const float* __restrict__ gt,
                                               const float* __restrict__ point,
                                               float* __restrict__ out) {
    const int b = blockIdx.x;
    const int t = threadIdx.x;

    __shared__ float4 sq[ANST][ACHUNK];       // 40 KB q stages (reused for points)
    __shared__ float red[80];
    __shared__ float Ms[9];
    __shared__ int isLast;

    const uint64_t pol = mkpolicy_evict_last();

    const float4* __restrict__ gq = (const float4*)(q + (size_t)b * KDIM * 4);
    const float*  __restrict__ gsf = s + (size_t)b * KDIM;
    const float4* __restrict__ gp = (const float4*)(point + (size_t)b * PDIM * 3);

    // Issue accum q-chunk c into stage st (2 cp.async / thread)
    auto issueA = [&](int c, int st) {
        unsigned dq = smem_u32(&sq[st][0]);
        const float4* srcq = gq + c * ACHUNK;
        cpa16(dq + t * 16,         srcq + t,       pol);
        cpa16(dq + (t + 256) * 16, srcq + t + 256, pol);
        cpa_commit();
    };
    // Issue a 768-float4 point chunk (3 cp.async / thread)
    auto issueP = [&](const float4* dstBase, int chunk) {
        unsigned d = smem_u32(dstBase);
        const float4* src = gp + chunk * 768;
        cpa16(d + t * 16,          src + t,       pol);
        cpa16(d + (t + 256) * 16,  src + t + 256, pol);
        cpa16(d + (t + 512) * 16,  src + t + 512, pol);
        cpa_commit();
    };

    // Pre-issue 4 q chunks; prefetch s for chunks 0 and 1 into registers.
    issueA(0, 0);
    issueA(1, 1);
    issueA(2, 2);
    issueA(3, 3);
    float sc0 = ldg_el(gsf + t, pol);
    float sc1 = ldg_el(gsf + t + 256, pol);
    float sn0 = ldg_el(gsf + ACHUNK + t, pol);
    float sn1 = ldg_el(gsf + ACHUNK + t + 256, pol);

    float a0 = 0.f, a1 = 0.f, a2 = 0.f, a3 = 0.f, a4 = 0.f;
    float a5 = 0.f, a6 = 0.f, a7 = 0.f, a8 = 0.f, a9 = 0.f;

    #pragma unroll
    for (int c = 0; c < ANCH; c++) {
        // Committed before wait at iter c: A0..A_{c+3}. wait<3> retires A_c.
        if (c < ANCH - 3)       cpa_wait<3>();
        else if (c == ANCH - 3) cpa_wait<2>();
        else if (c == ANCH - 2) cpa_wait<1>();
        else                    cpa_wait<0>();
        __syncthreads();

        // Prefetch s for chunk c+2 (overlaps with consume below).
        float sp0r = 0.f, sp1r = 0.f;
        if (c + 2 < ANCH) {
            sp0r = ldg_el(gsf + (c + 2) * ACHUNK + t, pol);
            sp1r = ldg_el(gsf + (c + 2) * ACHUNK + t + 256, pol);
        }

        const int st = c % ANST;
        const float4* q4s = &sq[st][0];
        float4 qa = q4s[t];
        float4 qb = q4s[t + 256];
        float w0 = fexp(sc0);
        float w1 = fexp(sc1);
        {
            float wr = w0 * qa.x, wi = w0 * qa.y, wj = w0 * qa.z, wk = w0 * qa.w;
            a0 += wr * qa.x; a1 += wr * qa.y; a2 += wr * qa.z; a3 += wr * qa.w;
            a4 += wi * qa.y; a5 += wi * qa.z; a6 += wi * qa.w;
            a7 += wj * qa.z; a8 += wj * qa.w; a9 += wk * qa.w;
        }
        {
            float wr = w1 * qb.x, wi = w1 * qb.y, wj = w1 * qb.z, wk = w1 * qb.w;
            a0 += wr * qb.x; a1 += wr * qb.y; a2 += wr * qb.z; a3 += wr * qb.w;
            a4 += wi * qb.y; a5 += wi * qb.z; a6 += wi * qb.w;
            a7 += wj * qb.z; a8 += wj * qb.w; a9 += wk * qb.w;
        }
        __syncthreads();   // all threads done reading stage st
        if (c + 4 < ANCH) issueA(c + 4, (c + 4) % ANST);

        // Rotate s double-buffer.
        sc0 = sn0; sc1 = sn1;
        sn0 = sp0r; sn1 = sp1r;
    }

    // Deterministic block reduction of the 10 accumulators.
    float acc[10] = {a0, a1, a2, a3, a4, a5, a6, a7, a8, a9};
    #pragma unroll
    for (int i = 0; i < 10; i++) acc[i] = warpSum(acc[i]);
    const int w = t >> 5, l = t & 31;
    if (l == 0) {
        #pragma unroll
        for (int i = 0; i < 10; i++) red[w * 10 + i] = acc[i];
    }
    __syncthreads();   // red ready; sq free (all accum groups drained)

    // Point buffers inside the 40 KB q region (3 x 768 float4 = 36 KB).
    float4* sp0 = &sq[0][0];
    float4* sp1 = &sq[0][0] + 768;
    float4* sp2 = &sq[0][0] + 1536;
    issueP(sp0, 0);    // P0
    issueP(sp1, 1);    // P1
    issueP(sp2, 2);    // P2

    // Thread 0: finish A, Jacobi eig, quat->mat difference -> Ms
    // (runs while P0/P1/P2 cp.asyncs are in flight).
    if (t == 0) {
        float A[10];
        #pragma unroll
        for (int i = 0; i < 10; i++) {
            float sA = 0.f;
            #pragma unroll
            for (int w2 = 0; w2 < 8; w2++) sA += red[w2 * 10 + i];
            A[i] = sA;
        }

        float a[4][4], v[4][4];
        a[0][0] = A[0];
        a[0][1] = a[1][0] = A[1];
        a[0][2] = a[2][0] = A[2];
        a[0][3] = a[3][0] = A[3];
        a[1][1] = A[4];
        a[1][2] = a[2][1] = A[5];
        a[1][3] = a[3][1] = A[6];
        a[2][2] = A[7];
        a[2][3] = a[3][2] = A[8];
        a[3][3] = A[9];
        #pragma unroll
        for (int i = 0; i < 4; i++)
            #pragma unroll
            for (int j = 0; j < 4; j++) v[i][j] = (i == j) ? 1.0f : 0.0f;

        const int PP[6] = {0, 0, 0, 1, 1, 2};
        const int QQ[6] = {1, 2, 3, 2, 3, 3};

        for (int sweep = 0; sweep < 6; sweep++) {
            #pragma unroll
            for (int pair = 0; pair < 6; pair++) {
                int p = PP[pair], qi = QQ[pair];
                float apq = a[p][qi];
                if (fabsf(apq) > 1e-30f) {
                    float theta = __fdividef(a[qi][qi] - a[p][p], 2.0f * apq);
                    float tt = __fdividef(1.0f, fabsf(theta) + sqrtf(theta * theta + 1.0f));
                    if (theta < 0.0f) tt = -tt;
                    float c = rsqrtf(tt * tt + 1.0f);
                    float sn = tt * c;
                    float app = a[p][p], aqq = a[qi][qi];
                    a[p][p] = app - tt * apq;
                    a[qi][qi] = aqq + tt * apq;
                    a[p][qi] = a[qi][p] = 0.0f;
                    #pragma unroll
                    for (int r = 0; r < 4; r++) {
                        if (r != p && r != qi) {
                            float arp = a[r][p], arq = a[r][qi];
                            a[r][p] = a[p][r] = c * arp - sn * arq;
                            a[r][qi] = a[qi][r] = sn * arp + c * arq;
                        }
                    }
                    #pragma unroll
                    for (int r = 0; r < 4; r++) {
                        float vrp = v[r][p], vrq = v[r][qi];
                        v[r][p] = c * vrp - sn * vrq;
                        v[r][qi] = sn * vrp + c * vrq;
                    }
                }
            }
        }

        int best = 0;
        float bv = a[0][0];
        #pragma unroll
        for (int i = 1; i < 4; i++)
            if (a[i][i] > bv) { bv = a[i][i]; best = i; }

        float qp[4] = {v[0][best], v[1][best], v[2][best], v[3][best]};
        // sign/norm of qp irrelevant: quat2mat divides by |q|^2 and is even in q
        float mp[9], mg[9];
        quat2mat(qp, mp);
        float qg[4] = {gt[b * 4 + 0], gt[b * 4 + 1], gt[b * 4 + 2], gt[b * 4 + 3]};
        quat2mat(qg, mg);
        #pragma unroll
        for (int i = 0; i < 9; i++) Ms[i] = mp[i] - mg[i];
    }
    __syncthreads();   // Ms visible; P0/P1/P2 committed by all threads
    const float M0 = Ms[0], M1 = Ms[1], M2 = Ms[2];
    const float M3 = Ms[3], M4 = Ms[4], M5 = Ms[5];
    const float M6 = Ms[6], M7 = Ms[7], M8 = Ms[8];

    // Consume one 1024-point chunk from an smem region.
    float pacc = 0.f;
    auto consumeP = [&](const float4* P) {
        float4 v0 = P[3 * t + 0];
        float4 v1 = P[3 * t + 1];
        float4 v2 = P[3 * t + 2];
        float px[4] = {v0.x, v0.w, v1.z, v2.y};
        float py[4] = {v0.y, v1.x, v1.w, v2.z};
        float pz[4] = {v0.z, v1.y, v2.x, v2.w};
        #pragma unroll
        for (int r = 0; r < 4; r++) {
            float x = px[r], y = py[r], z = pz[r];
            float dx = x * M0 + y * M3 + z * M6;
            float dy = x * M1 + y * M4 + z * M7;
            float dz = x * M2 + y * M5 + z * M8;
            pacc += fsqrt_fma(dx * dx + dy * dy + dz * dz);
        }
    };

    cpa_wait<2>();             // pending <= 2 {P1,P2} => P0 done
    __syncthreads();
    consumeP(sp0);             // chunk 0
    __syncthreads();           // all threads done reading sp0
    issueP(sp0, 3);            // P3 reuses sp0
    cpa_wait<2>();             // pending <= 2 {P2,P3} => P1 done
    __syncthreads();
    consumeP(sp1);             // chunk 1
    cpa_wait<1>();             // P2 done
    __syncthreads();
    consumeP(sp2);             // chunk 2
    cpa_wait<0>();             // P3 done
    __syncthreads();
    consumeP(sp0);             // chunk 3

    // Block reduction of point sum.
    pacc = warpSum(pacc);
    if (l == 0) red[w] = pacc;
    __syncthreads();
    if (t < 32) {
        float x = (t < 8) ? red[t] : 0.f;
        x = warpSum(x);
        if (t == 0) g_part[b] = x;
    }

    // Last-block-done final reduction (deterministic fixed-order sum).
    if (t == 0) {
        __threadfence();
        unsigned int prev = atomicAdd(&g_cnt, 1u);
        isLast = (prev == (unsigned)(BDIM - 1));
    }
    __syncthreads();
    if (isLast) {
        float sfin = g_part[t] + g_part[t + 256];
        sfin = warpSum(sfin);
        if ((t & 31) == 0) red[t >> 5] = sfin;
        __syncthreads();
        if (t < 32) {
            float x = (t < 8) ? red[t] : 0.f;
            x = warpSum(x);
            if (t == 0) {
                out[0] = x * (1.0f / ((float)BDIM * (float)PDIM));
                g_cnt = 0u;   // reset for next graph replay
            }
        }
    }
}

extern "C" void kernel_launch(void* const* d_in, const int* in_sizes, int n_in,
                              void* d_out, int out_size) {
    const float* s     = (const float*)d_in[0];  // softEncodePred (B,K)
    const float* q     = (const float*)d_in[1];  // oriHistogramMap (B,K,4)
    const float* gt    = (const float*)d_in[2];  // gt (B,4)
    const float* point = (const float*)d_in[3];  // point (B,P,3)
    float* out = (float*)d_out;

    k_fused<<<BDIM, 256>>>(s, q, gt, point, out);
}

// round 11
// speedup vs baseline: 1.2311x; 1.0682x over previous
#include <cuda_runtime.h>
#include <math.h>
#include <stdint.h>

#define KDIM 8192
#define BDIM 512
#define PDIM 4096

#define ACHUNK 512                 // k's per accum chunk (8 KB of q)
#define ANCH   (KDIM / ACHUNK)     // 16 accum chunks
#define ANST   5                   // q stages (8 KB each)
#define ABYTES (ACHUNK * 16)       // 8192 B per q chunk
#define PBYTES (1024 * 12)         // 12288 B per point chunk (1024 pts)

// Scratch (allocation-free rule: __device__ globals)
__device__ float g_part[BDIM];       // per-block point partial sums
__device__ unsigned int g_cnt;       // last-block-done counter (self-reset)

__device__ __forceinline__ float warpSum(float v) {
    #pragma unroll
    for (int o = 16; o; o >>= 1) v += __shfl_xor_sync(0xffffffffu, v, o);
    return v;
}

__device__ __forceinline__ unsigned smem_u32(const void* p) {
    return (unsigned)__cvta_generic_to_shared(p);
}

// ---- mbarrier + TMA bulk helpers -----------------------------------------
__device__ __forceinline__ void mbar_init(unsigned mbar, unsigned count) {
    asm volatile("mbarrier.init.shared.b64 [%0], %1;" :: "r"(mbar), "r"(count) : "memory");
}
__device__ __forceinline__ void mbar_expect_tx(unsigned mbar, unsigned bytes) {
    asm volatile("mbarrier.arrive.expect_tx.shared.b64 _, [%0], %1;"
                 :: "r"(mbar), "r"(bytes) : "memory");
}
__device__ __forceinline__ void mbar_wait(unsigned mbar, unsigned parity) {
    asm volatile(
        "{\n\t"
        ".reg .pred P1;\n\t"
        "WAIT_LOOP_%=:\n\t"
        "mbarrier.try_wait.parity.acquire.cta.shared::cta.b64 P1, [%0], %1, 0x989680;\n\t"
        "@P1 bra.uni WAIT_DONE_%=;\n\t"
        "bra.uni WAIT_LOOP_%=;\n\t"
        "WAIT_DONE_%=:\n\t"
        "}"
        :: "r"(mbar), "r"(parity) : "memory");
}
// 1D bulk copy global -> shared, completion via mbarrier tx-bytes.
__device__ __forceinline__ void bulk_g2s(unsigned dst, const void* src,
                                         unsigned bytes, unsigned mbar) {
    asm volatile(
        "cp.async.bulk.shared::cta.global.mbarrier::complete_tx::bytes [%0], [%1], %2, [%3];"
        :: "r"(dst), "l"(src), "r"(bytes), "r"(mbar) : "memory");
}

// FMA/ALU-pipe exp (no MUFU). |x| <= ~20, rel err ~1.5e-7.
__device__ __forceinline__ float fexp(float x) {
    float t  = x * 1.4426950408889634f;
    float fn = t + 12582912.0f;
    int   n  = __float_as_int(fn) - 0x4B400000;
    float r  = t - (fn - 12582912.0f);
    float p = 1.5403530393e-4f;
    p = fmaf(p, r, 1.3333558146e-3f);
    p = fmaf(p, r, 9.6181291076e-3f);
    p = fmaf(p, r, 5.5504108665e-2f);
    p = fmaf(p, r, 2.4022650696e-1f);
    p = fmaf(p, r, 6.9314718056e-1f);
    p = fmaf(p, r, 1.0f);
    return __int_as_float(__float_as_int(p) + (n << 23));
}

// FMA/ALU-pipe sqrt: magic rsqrt + 2 Newton iters, then c * rsqrt(c).
__device__ __forceinline__ float fsqrt_fma(float c) {
    float y = __int_as_float(0x5f3759df - (__float_as_int(c) >> 1));
    float h = 0.5f * c;
    y = y * fmaf(-h * y, y, 1.5f);
    y = y * fmaf(-h * y, y, 1.5f);
    return c * y;
}

__device__ __forceinline__ void quat2mat(const float qv[4], float mm[9]) {
    float r = qv[0], i = qv[1], j = qv[2], k = qv[3];
    float two_s = __fdividef(2.0f, r * r + i * i + j * j + k * k);
    mm[0] = 1.0f - two_s * (j * j + k * k);
    mm[1] = two_s * (i * j - k * r);
    mm[2] = two_s * (i * k + j * r);
    mm[3] = two_s * (i * j + k * r);
    mm[4] = 1.0f - two_s * (i * i + k * k);
    mm[5] = two_s * (j * k - i * r);
    mm[6] = two_s * (i * k - j * r);
    mm[7] = two_s * (j * k + i * r);
    mm[8] = 1.0f - two_s * (i * i + j * j);
}

// ---------------------------------------------------------------------------
// One fused kernel, one CTA per batch (grid 512).
// q + point data move via cp.async.bulk (TMA/UBLKCP, one 8-12 KB bulk per
// chunk issued by thread 0) with mbarrier tx-completion; s stays on a
// register double-buffer of coalesced LDGs. Inline eig + last-block mean.
// ---------------------------------------------------------------------------
__global__ __launch_bounds__(256) void k_fused(const float* __restrict__ s,
                                               const float* __restrict__ q,
                                               const float* __restrict__ gt,
                                               const float* __restrict__ point,
                                               float* __restrict__ out) {
    const int b = blockIdx.x;
    const int t = threadIdx.x;

    __shared__ float4 sq[ANST][ACHUNK];            // 40 KB q stages (reused for points)
    __shared__ alignas(8) unsigned long long ambar[ANST];  // accum stage barriers
    __shared__ alignas(8) unsigned long long pmbar[4];     // one-shot point barriers
    __shared__ float red[80];
    __shared__ float Ms[9];
    __shared__ int isLast;

    const float4* __restrict__ gq = (const float4*)(q + (size_t)b * KDIM * 4);
    const float*  __restrict__ gsf = s + (size_t)b * KDIM;
    const char*   __restrict__ gpc = (const char*)(point + (size_t)b * PDIM * 3);

    // Init barriers (thread 0), then make them visible.
    if (t == 0) {
        #pragma unroll
        for (int i = 0; i < ANST; i++) mbar_init(smem_u32(&ambar[i]), 1);
        #pragma unroll
        for (int i = 0; i < 4; i++)    mbar_init(smem_u32(&pmbar[i]), 1);
    }
    __syncthreads();

    // Thread-0 issue of accum chunk c (one 8 KB bulk into stage c%ANST).
    auto issueA = [&](int c) {
        const int st = c % ANST;
        unsigned mb = smem_u32(&ambar[st]);
        mbar_expect_tx(mb, ABYTES);
        bulk_g2s(smem_u32(&sq[st][0]), gq + c * ACHUNK, ABYTES, mb);
    };
    // Thread-0 issue of point chunk (12 KB bulk) with its own barrier.
    auto issueP = [&](const float4* dstBase, int chunk, int bar) {
        unsigned mb = smem_u32(&pmbar[bar]);
        mbar_expect_tx(mb, PBYTES);
        bulk_g2s(smem_u32(dstBase), gpc + (size_t)chunk * PBYTES, PBYTES, mb);
    };

    if (t == 0) { issueA(0); issueA(1); issueA(2); issueA(3); }

    // s double-buffer in registers.
    float sc0 = gsf[t], sc1 = gsf[t + 256];
    float sn0 = gsf[ACHUNK + t], sn1 = gsf[ACHUNK + t + 256];

    float a0 = 0.f, a1 = 0.f, a2 = 0.f, a3 = 0.f, a4 = 0.f;
    float a5 = 0.f, a6 = 0.f, a7 = 0.f, a8 = 0.f, a9 = 0.f;

    #pragma unroll
    for (int c = 0; c < ANCH; c++) {
        const int st = c % ANST;
        mbar_wait(smem_u32(&ambar[st]), (unsigned)((c / ANST) & 1));

        // Prefetch s for chunk c+2 (overlaps consume).
        float sp0r = 0.f, sp1r = 0.f;
        if (c + 2 < ANCH) {
            sp0r = gsf[(c + 2) * ACHUNK + t];
            sp1r = gsf[(c + 2) * ACHUNK + t + 256];
        }

        const float4* q4s = &sq[st][0];
        float4 qa = q4s[t];
        float4 qb = q4s[t + 256];
        float w0 = fexp(sc0);
        float w1 = fexp(sc1);
        {
            float wr = w0 * qa.x, wi = w0 * qa.y, wj = w0 * qa.z, wk = w0 * qa.w;
            a0 += wr * qa.x; a1 += wr * qa.y; a2 += wr * qa.z; a3 += wr * qa.w;
            a4 += wi * qa.y; a5 += wi * qa.z; a6 += wi * qa.w;
            a7 += wj * qa.z; a8 += wj * qa.w; a9 += wk * qa.w;
        }
        {
            float wr = w1 * qb.x, wi = w1 * qb.y, wj = w1 * qb.z, wk = w1 * qb.w;
            a0 += wr * qb.x; a1 += wr * qb.y; a2 += wr * qb.z; a3 += wr * qb.w;
            a4 += wi * qb.y; a5 += wi * qb.z; a6 += wi * qb.w;
            a7 += wj * qb.z; a8 += wj * qb.w; a9 += wk * qb.w;
        }
        __syncthreads();   // all threads done reading stage st's PREVIOUS victim
        // Stage (c+4)%ANST was last read at iter c-1 (finished by that iter's
        // barrier, which precedes this one) => safe to overwrite.
        if (c + 4 < ANCH && t == 0) issueA(c + 4);

        sc0 = sn0; sc1 = sn1;
        sn0 = sp0r; sn1 = sp1r;
    }

    // Deterministic block reduction of the 10 accumulators.
    float acc[10] = {a0, a1, a2, a3, a4, a5, a6, a7, a8, a9};
    #pragma unroll
    for (int i = 0; i < 10; i++) acc[i] = warpSum(acc[i]);
    const int w = t >> 5, l = t & 31;
    if (l == 0) {
        #pragma unroll
        for (int i = 0; i < 10; i++) red[w * 10 + i] = acc[i];
    }
    __syncthreads();   // red ready; all accum bulks complete & consumed => sq free

    // Point buffers inside the 40 KB q region (3 x 768 float4 = 36 KB).
    float4* sp0 = &sq[0][0];
    float4* sp1 = &sq[0][0] + 768;
    float4* sp2 = &sq[0][0] + 1536;
    if (t == 0) { issueP(sp0, 0, 0); issueP(sp1, 1, 1); issueP(sp2, 2, 2); }

    // Thread 0: finish A, Jacobi eig, quat->mat difference -> Ms
    // (runs while the point bulks are in flight).
    if (t == 0) {
        float A[10];
        #pragma unroll
        for (int i = 0; i < 10; i++) {
            float sA = 0.f;
            #pragma unroll
            for (int w2 = 0; w2 < 8; w2++) sA += red[w2 * 10 + i];
            A[i] = sA;
        }

        float a[4][4], v[4][4];
        a[0][0] = A[0];
        a[0][1] = a[1][0] = A[1];
        a[0][2] = a[2][0] = A[2];
        a[0][3] = a[3][0] = A[3];
        a[1][1] = A[4];
        a[1][2] = a[2][1] = A[5];
        a[1][3] = a[3][1] = A[6];
        a[2][2] = A[7];
        a[2][3] = a[3][2] = A[8];
        a[3][3] = A[9];
        #pragma unroll
        for (int i = 0; i < 4; i++)
            #pragma unroll
            for (int j = 0; j < 4; j++) v[i][j] = (i == j) ? 1.0f : 0.0f;

        const int PP[6] = {0, 0, 0, 1, 1, 2};
        const int QQ[6] = {1, 2, 3, 2, 3, 3};

        for (int sweep = 0; sweep < 6; sweep++) {
            #pragma unroll
            for (int pair = 0; pair < 6; pair++) {
                int p = PP[pair], qi = QQ[pair];
                float apq = a[p][qi];
                if (fabsf(apq) > 1e-30f) {
                    float theta = __fdividef(a[qi][qi] - a[p][p], 2.0f * apq);
                    float tt = __fdividef(1.0f, fabsf(theta) + sqrtf(theta * theta + 1.0f));
                    if (theta < 0.0f) tt = -tt;
                    float c = rsqrtf(tt * tt + 1.0f);
                    float sn = tt * c;
                    float app = a[p][p], aqq = a[qi][qi];
                    a[p][p] = app - tt * apq;
                    a[qi][qi] = aqq + tt * apq;
                    a[p][qi] = a[qi][p] = 0.0f;
                    #pragma unroll
                    for (int r = 0; r < 4; r++) {
                        if (r != p && r != qi) {
                            float arp = a[r][p], arq = a[r][qi];
                            a[r][p] = a[p][r] = c * arp - sn * arq;
                            a[r][qi] = a[qi][r] = sn * arp + c * arq;
                        }
                    }
                    #pragma unroll
                    for (int r = 0; r < 4; r++) {
                        float vrp = v[r][p], vrq = v[r][qi];
                        v[r][p] = c * vrp - sn * vrq;
                        v[r][qi] = sn * vrp + c * vrq;
                    }
                }
            }
        }

        int best = 0;
        float bv = a[0][0];
        #pragma unroll
        for (int i = 1; i < 4; i++)
            if (a[i][i] > bv) { bv = a[i][i]; best = i; }

        float qp[4] = {v[0][best], v[1][best], v[2][best], v[3][best]};
        // sign/norm of qp irrelevant: quat2mat divides by |q|^2 and is even in q
        float mp[9], mg[9];
        quat2mat(qp, mp);
        float qg[4] = {gt[b * 4 + 0], gt[b * 4 + 1], gt[b * 4 + 2], gt[b * 4 + 3]};
        quat2mat(qg, mg);
        #pragma unroll
        for (int i = 0; i < 9; i++) Ms[i] = mp[i] - mg[i];
    }
    __syncthreads();   // Ms visible
    const float M0 = Ms[0], M1 = Ms[1], M2 = Ms[2];
    const float M3 = Ms[3], M4 = Ms[4], M5 = Ms[5];
    const float M6 = Ms[6], M7 = Ms[7], M8 = Ms[8];

    // Consume one 1024-point chunk from an smem region.
    float pacc = 0.f;
    auto consumeP = [&](const float4* P) {
        float4 v0 = P[3 * t + 0];
        float4 v1 = P[3 * t + 1];
        float4 v2 = P[3 * t + 2];
        float px[4] = {v0.x, v0.w, v1.z, v2.y};
        float py[4] = {v0.y, v1.x, v1.w, v2.z};
        float pz[4] = {v0.z, v1.y, v2.x, v2.w};
        #pragma unroll
        for (int r = 0; r < 4; r++) {
            float x = px[r], y = py[r], z = pz[r];
            float dx = x * M0 + y * M3 + z * M6;
            float dy = x * M1 + y * M4 + z * M7;
            float dz = x * M2 + y * M5 + z * M8;
            pacc += fsqrt_fma(dx * dx + dy * dy + dz * dz);
        }
    };

    mbar_wait(smem_u32(&pmbar[0]), 0u);
    consumeP(sp0);             // chunk 0
    __syncthreads();           // all threads done reading sp0
    if (t == 0) issueP(sp0, 3, 3);   // P3 reuses sp0, fresh barrier
    mbar_wait(smem_u32(&pmbar[1]), 0u);
    consumeP(sp1);             // chunk 1
    mbar_wait(smem_u32(&pmbar[2]), 0u);
    consumeP(sp2);             // chunk 2
    mbar_wait(smem_u32(&pmbar[3]), 0u);
    consumeP(sp0);             // chunk 3

    // Block reduction of point sum.
    pacc = warpSum(pacc);
    if (l == 0) red[w] = pacc;
    __syncthreads();
    if (t < 32) {
        float x = (t < 8) ? red[t] : 0.f;
        x = warpSum(x);
        if (t == 0) g_part[b] = x;
    }

    // Last-block-done final reduction (deterministic fixed-order sum).
    if (t == 0) {
        __threadfence();
        unsigned int prev = atomicAdd(&g_cnt, 1u);
        isLast = (prev == (unsigned)(BDIM - 1));
    }
    __syncthreads();
    if (isLast) {
        float sfin = g_part[t] + g_part[t + 256];
        sfin = warpSum(sfin);
        if ((t & 31) == 0) red[t >> 5] = sfin;
        __syncthreads();
        if (t < 32) {
            float x = (t < 8) ? red[t] : 0.f;
            x = warpSum(x);
            if (t == 0) {
                out[0] = x * (1.0f / ((float)BDIM * (float)PDIM));
                g_cnt = 0u;   // reset for next graph replay
            }
        }
    }
}

extern "C" void kernel_launch(void* const* d_in, const int* in_sizes, int n_in,
                              void* d_out, int out_size) {
    const float* s     = (const float*)d_in[0];  // softEncodePred (B,K)
    const float* q     = (const float*)d_in[1];  // oriHistogramMap (B,K,4)
    const float* gt    = (const float*)d_in[2];  // gt (B,4)
    const float* point = (const float*)d_in[3];  // point (B,P,3)
    float* out = (float*)d_out;

    k_fused<<<BDIM, 256>>>(s, q, gt, point, out);
}